// round 9
// baseline (speedup 1.0000x reference)
#include <cuda_runtime.h>
#include <cuda_bf16.h>
#include <cuda_fp16.h>
#include <cstdint>
#include <math.h>

// Problem constants (fixed shapes from setup_inputs)
#define BB 2
#define CC 64
#define LL 4096   // H*W = 64*64
#define NT 32     // 4096/128 tiles per dim

// Scratch
__device__ float    g_S[(size_t)BB * LL * LL];          // score matrix, 128 MiB
__device__ uint32_t g_Pbh32[(size_t)BB * LL * LL / 2];  // attn rows bf16 hi (packed pairs)
__device__ uint32_t g_Pbl32[(size_t)BB * LL * LL / 2];  // attn rows bf16 lo
__device__ uint32_t g_Fbh32[(size_t)BB * 64 * LL / 2];  // former bf16 hi
__device__ uint32_t g_Fbl32[(size_t)BB * 64 * LL / 2];  // former bf16 lo
__device__ float    g_part[(size_t)BB * 4 * LL * 64];   // K-split partials, 8 MiB
__device__ float    g_invn[BB * LL];
__device__ int      g_flag[LL];
__device__ int      g_list[LL];
__device__ int      g_nflag;

// ---------------------------------------------------------------------------
// mma.sync helpers (arch-agnostic: sm_80+ PTX, no tcgen05)
// ---------------------------------------------------------------------------
__device__ __forceinline__ uint32_t smem_u32(const void* p) {
    uint32_t a;
    asm("{ .reg .u64 t; cvta.to.shared.u64 t, %1; cvt.u32.u64 %0, t; }"
        : "=r"(a) : "l"(p));
    return a;
}
__device__ __forceinline__ void ldsm_x4(uint32_t* r, uint32_t addr) {
    asm volatile("ldmatrix.sync.aligned.m8n8.x4.shared.b16 {%0,%1,%2,%3}, [%4];"
                 : "=r"(r[0]), "=r"(r[1]), "=r"(r[2]), "=r"(r[3]) : "r"(addr));
}
__device__ __forceinline__ void mma_bf16(float* d, const uint32_t* a, const uint32_t* b) {
    asm volatile(
        "mma.sync.aligned.m16n8k16.row.col.f32.bf16.bf16.f32 "
        "{%0,%1,%2,%3}, {%4,%5,%6,%7}, {%8,%9}, {%0,%1,%2,%3};"
        : "+f"(d[0]), "+f"(d[1]), "+f"(d[2]), "+f"(d[3])
        : "r"(a[0]), "r"(a[1]), "r"(a[2]), "r"(a[3]), "r"(b[0]), "r"(b[1]));
}
#define SW128(o) ((o) ^ (((o) >> 3) & 0x70))

__device__ __forceinline__ uint32_t pack_bf16_hi(float v0, float v1) {
    unsigned short h0 = __bfloat16_as_ushort(__float2bfloat16(v0));
    unsigned short h1 = __bfloat16_as_ushort(__float2bfloat16(v1));
    return (uint32_t)h0 | ((uint32_t)h1 << 16);
}
__device__ __forceinline__ uint32_t pack_bf16_lo(float v0, float v1, uint32_t hi) {
    float h0 = __bfloat162float(__ushort_as_bfloat16((unsigned short)(hi & 0xFFFF)));
    float h1 = __bfloat162float(__ushort_as_bfloat16((unsigned short)(hi >> 16)));
    unsigned short l0 = __bfloat16_as_ushort(__float2bfloat16(v0 - h0));
    unsigned short l1 = __bfloat16_as_ushort(__float2bfloat16(v1 - h1));
    return (uint32_t)l0 | ((uint32_t)l1 << 16);
}

// ---------------------------------------------------------------------------
// Kernel 0: copy former+latter into out channels [0,128), zero shift [128,192)
// ---------------------------------------------------------------------------
__global__ void k_init_out(const float* __restrict__ x, float* __restrict__ out) {
    int idx = blockIdx.x * blockDim.x + threadIdx.x;
    const int total = BB * 192 * LL;
    if (idx >= total) return;
    int b  = idx / (192 * LL);
    int r  = idx - b * (192 * LL);
    int ch = r >> 12;
    int l  = r & (LL - 1);
    float v = 0.0f;
    if (ch < 128) v = x[((size_t)b * 128 + ch) * LL + l];
    out[idx] = v;
}

// ---------------------------------------------------------------------------
// Kernel 0b: convert former to bf16 hi/lo planes (packed pairs)
// ---------------------------------------------------------------------------
__global__ void k_fconv(const float* __restrict__ x) {
    int p = blockIdx.x * blockDim.x + threadIdx.x;
    const int total = BB * 64 * (LL / 2);
    if (p >= total) return;
    int b   = p / (64 * (LL / 2));
    int rem = p - b * (64 * (LL / 2));
    int ch  = rem / (LL / 2);
    int cp  = rem - ch * (LL / 2);
    const float* src = x + ((size_t)(b * 128 + ch)) * LL + cp * 2;
    float v0 = src[0], v1 = src[1];
    uint32_t hi = pack_bf16_hi(v0, v1);
    g_Fbh32[p] = hi;
    g_Fbl32[p] = pack_bf16_lo(v0, v1, hi);
}

// ---------------------------------------------------------------------------
// Kernel 1: per-(b,k) inverse norm of latter column, and flags from mask
// ---------------------------------------------------------------------------
__global__ void k_prep(const float* __restrict__ x, const float* __restrict__ mask) {
    int t = blockIdx.x * blockDim.x + threadIdx.x;
    if (t >= BB * LL) return;
    int b = t >> 12;
    int k = t & (LL - 1);
    const float* lat = x + ((size_t)b * 128 + 64) * LL;
    float s = 0.0f;
    #pragma unroll
    for (int c = 0; c < CC; c++) {
        float v = lat[(size_t)c * LL + k];
        s += v * v;
    }
    g_invn[t] = 1.0f / fmaxf(sqrtf(s), 1e-4f);
    if (t < LL) g_flag[t] = (mask[t] > 0.5f) ? 1 : 0;
}

// ---------------------------------------------------------------------------
// Kernel 1b: deterministic compaction of flagged indices (single block)
// ---------------------------------------------------------------------------
__global__ void k_compact() {
    __shared__ int cnt[256];
    int t = threadIdx.x;
    int base_l = t * 16;
    int fl[16];
    #pragma unroll
    for (int q = 0; q < 4; q++) {
        int4 v = *(const int4*)&g_flag[base_l + q * 4];
        fl[q * 4 + 0] = v.x; fl[q * 4 + 1] = v.y;
        fl[q * 4 + 2] = v.z; fl[q * 4 + 3] = v.w;
    }
    int c = 0;
    #pragma unroll
    for (int j = 0; j < 16; j++) c += fl[j];
    cnt[t] = c;
    __syncthreads();
    for (int off = 1; off < 256; off <<= 1) {
        int v = (t >= off) ? cnt[t - off] : 0;
        __syncthreads();
        cnt[t] += v;
        __syncthreads();
    }
    int pos = cnt[t] - c;
    #pragma unroll
    for (int j = 0; j < 16; j++) {
        if (fl[j]) g_list[pos++] = base_l + j;
    }
    if (t == 255) g_nflag = cnt[255];
}

// ---------------------------------------------------------------------------
// Kernel 2: mma.sync bf16x3 score GEMM, SYMMETRIC (upper tiles only).
// G[m][n] symmetric: compute tile (tm<=tn), store
//   S[m][n] = G*invn[n]  (regs)      S[n][m] = G*invn[m]  (smem transpose)
// smem: operand planes (64KB) aliased by 128x132 f32 transpose stage (67.6KB).
// ---------------------------------------------------------------------------
#define SM_AHI    0
#define SM_ALO    16384
#define SM_BHI    32768
#define SM_BLO    49152
#define SM_INVN_N 67584
#define SM_INVN_M 68096
#define SM_DYN    68608

__global__ __launch_bounds__(256) void k_gemm_mma(const float* __restrict__ x) {
    extern __shared__ char smem[];
    uint32_t sbase = smem_u32(smem);
    int tid  = threadIdx.x;
    int b  = blockIdx.y;

    // decode upper-triangular tile index
    int tt = blockIdx.x, tm = 0;
    while (tt >= NT - tm) { tt -= NT - tm; tm++; }
    int tn = tm + tt;
    int m0 = tm * 128, n0 = tn * 128;

    const float* lat = x + ((size_t)b * 128 + 64) * LL;
    float* invn_n = (float*)(smem + SM_INVN_N);
    float* invn_m = (float*)(smem + SM_INVN_M);
    if (tid < 128) {
        invn_n[tid] = g_invn[b * LL + n0 + tid];
        invn_m[tid] = g_invn[b * LL + m0 + tid];
    }

    {
        int side = tid >> 7;                  // 0 = A(m), 1 = B(n)
        int r    = tid & 127;
        const float* src = lat + (side ? n0 : m0) + r;
        char* dhi = smem + (side ? SM_BHI : SM_AHI);
        char* dlo = smem + (side ? SM_BLO : SM_ALO);
        #pragma unroll 8
        for (int c0 = 0; c0 < CC; c0 += 2) {
            float v0 = src[(size_t)c0 * LL];
            float v1 = src[(size_t)(c0 + 1) * LL];
            uint32_t hi = pack_bf16_hi(v0, v1);
            uint32_t lo = pack_bf16_lo(v0, v1, hi);
            uint32_t off = SW128((uint32_t)(r * 128 + c0 * 2));
            *(uint32_t*)(dhi + off) = hi;
            *(uint32_t*)(dlo + off) = lo;
        }
    }
    __syncthreads();

    int wid  = tid >> 5;
    int lane = tid & 31;
    int wm = (wid & 3) * 32;
    int wn = (wid >> 2) * 64;
    int j  = lane & 7;
    int g  = lane >> 3;

    float acc[2][8][4];
    #pragma unroll
    for (int mi = 0; mi < 2; mi++)
        #pragma unroll
        for (int t = 0; t < 8; t++)
            #pragma unroll
            for (int q = 0; q < 4; q++) acc[mi][t][q] = 0.0f;

    #pragma unroll
    for (int kc = 0; kc < 4; kc++) {
        int kb = kc * 32;

        uint32_t a_hi[2][4], a_lo[2][4], b_hi[4][4], b_lo[4][4];
        #pragma unroll
        for (int mi = 0; mi < 2; mi++) {
            uint32_t row = wm + mi * 16 + (g & 1) * 8 + j;
            uint32_t kby = kb + (g >> 1) * 16;
            uint32_t off = SW128(row * 128 + kby);
            ldsm_x4(a_hi[mi], sbase + SM_AHI + off);
            ldsm_x4(a_lo[mi], sbase + SM_ALO + off);
        }
        #pragma unroll
        for (int tp = 0; tp < 4; tp++) {
            uint32_t row = wn + tp * 16 + (g >> 1) * 8 + j;
            uint32_t kby = kb + (g & 1) * 16;
            uint32_t off = SW128(row * 128 + kby);
            ldsm_x4(b_hi[tp], sbase + SM_BHI + off);
            ldsm_x4(b_lo[tp], sbase + SM_BLO + off);
        }

        #pragma unroll
        for (int mi = 0; mi < 2; mi++)
            #pragma unroll
            for (int t = 0; t < 8; t++) {
                const uint32_t* bh = &b_hi[t >> 1][(t & 1) * 2];
                const uint32_t* bl = &b_lo[t >> 1][(t & 1) * 2];
                mma_bf16(acc[mi][t], a_hi[mi], bh);
                mma_bf16(acc[mi][t], a_hi[mi], bl);
                mma_bf16(acc[mi][t], a_lo[mi], bh);
            }
    }

    float* Sp = g_S + (size_t)b * LL * LL;
    bool offdiag = (tm != tn);

    if (offdiag) __syncthreads();   // all warps done reading operand smem

    // ---- normal-side store (regs), and stage raw G into Ts if off-diagonal
    float* Ts = (float*)smem;       // [128][132], aliases operand planes
    #pragma unroll
    for (int t = 0; t < 8; t++) {
        int n = wn + t * 8 + (lane & 3) * 2;
        float2 w = *(float2*)&invn_n[n];
        #pragma unroll
        for (int mi = 0; mi < 2; mi++) {
            int rl = wm + mi * 16 + (lane >> 2);
            int r0 = m0 + rl;
            float* p0 = &Sp[(size_t)r0 * LL + n0 + n];
            float* p1 = &Sp[(size_t)(r0 + 8) * LL + n0 + n];
            *(float2*)p0 = make_float2(acc[mi][t][0] * w.x, acc[mi][t][1] * w.y);
            *(float2*)p1 = make_float2(acc[mi][t][2] * w.x, acc[mi][t][3] * w.y);
            if (offdiag) {
                Ts[rl * 132 + n]           = acc[mi][t][0];
                Ts[rl * 132 + n + 1]       = acc[mi][t][1];
                Ts[(rl + 8) * 132 + n]     = acc[mi][t][2];
                Ts[(rl + 8) * 132 + n + 1] = acc[mi][t][3];
            }
        }
    }

    // ---- transposed-side store: S[n0+nn][m0+c] = Ts[c][nn] * invn_m[c]
    if (offdiag) {
        __syncthreads();
        int nn = tid >> 1;
        int c0 = (tid & 1) * 64;
        float* outrow = Sp + (size_t)(n0 + nn) * LL + m0 + c0;
        #pragma unroll
        for (int q = 0; q < 16; q++) {
            int c = c0 + q * 4;
            float4 v;
            v.x = Ts[(c + 0) * 132 + nn] * invn_m[c + 0];
            v.y = Ts[(c + 1) * 132 + nn] * invn_m[c + 1];
            v.z = Ts[(c + 2) * 132 + nn] * invn_m[c + 2];
            v.w = Ts[(c + 3) * 132 + nn] * invn_m[c + 3];
            *(float4*)&outrow[q * 4] = v;
        }
    }
}

// ---------------------------------------------------------------------------
// Kernel 3: per flagged row: 9-point fused gather, 4-wide vectorized + masked
// softmax with f16x2 exp (2 exps per MUFU op); write bf16 hi/lo attn planes.
// ---------------------------------------------------------------------------
__global__ __launch_bounds__(256) void k_softmax() {
    int ii = blockIdx.x;
    if (ii >= g_nflag) return;
    int l = g_list[ii];
    int b = blockIdx.y;

    __shared__ float row[LL];
    __shared__ float red[256];

    const float* S = g_S + (size_t)b * LL * LL;
    int tid = threadIdx.x;

    int hl = l >> 6, wl = l & 63;
    int ml = (wl << 6) | hl;

    const float* rp[3][3];
    bool rv[3][3];
    #pragma unroll
    for (int ei = 0; ei < 3; ei++) {
        int m2 = ml + ei - 1;
        bool v = (m2 >= 0 && m2 < LL);
        int l2v = v ? (((m2 & 63) << 6) | (m2 >> 6)) : 0;
        #pragma unroll
        for (int di = 0; di < 3; di++) {
            int r = l2v + di - 1;
            bool ok = v && (r >= 0 && r < LL);
            rv[ei][di] = ok;
            rp[ei][di] = ok ? (S + (size_t)r * LL) : S;
        }
    }

    float mx = -INFINITY;
    for (int idx = tid; idx < LL / 4; idx += 256) {
        int k0 = idx * 4;
        int h  = k0 >> 6;
        int w0 = k0 & 63;
        float a0 = 0.f, a1 = 0.f, a2 = 0.f, a3 = 0.f;

        #pragma unroll
        for (int ei = 0; ei < 3; ei++) {
            int hh = h + ei - 1;
            if (hh >= 0 && hh < 64) {
                int k2 = (hh << 6) | w0;
                #pragma unroll
                for (int di = 0; di < 3; di++) {
                    if (!rv[ei][di]) continue;
                    const float* rw = rp[ei][di];
                    float4 v = *(const float4*)&rw[k2];
                    if (di == 0) {
                        float vl = (k2 >= 1) ? rw[k2 - 1] : 0.0f;
                        a0 += vl;  a1 += v.x; a2 += v.y; a3 += v.z;
                    } else if (di == 1) {
                        a0 += v.x; a1 += v.y; a2 += v.z; a3 += v.w;
                    } else {
                        float vr = (k2 + 4 < LL) ? rw[k2 + 4] : 0.0f;
                        a0 += v.y; a1 += v.z; a2 += v.w; a3 += vr;
                    }
                }
            } else {
                bool neg = (hh < 0);
                float* accp[4] = {&a0, &a1, &a2, &a3};
                #pragma unroll
                for (int j = 0; j < 4; j++) {
                    int w = w0 + j;
                    int k2; bool kv;
                    if (neg) { k2 = 4032 + (w - 1); kv = (w >= 1); }
                    else     { k2 = w + 1;          kv = (w <= 62); }
                    if (!kv) continue;
                    #pragma unroll
                    for (int di = 0; di < 3; di++) {
                        int c = k2 + di - 1;
                        if (rv[ei][di] && c >= 0 && c < LL)
                            *accp[j] += rp[ei][di][c];
                    }
                }
            }
        }

        int4 fl = *(const int4*)&g_flag[k0];
        float v0 = fl.x ? -INFINITY : a0;
        float v1 = fl.y ? -INFINITY : a1;
        float v2 = fl.z ? -INFINITY : a2;
        float v3 = fl.w ? -INFINITY : a3;
        *(float4*)&row[k0] = make_float4(v0, v1, v2, v3);
        mx = fmaxf(mx, fmaxf(fmaxf(v0, v1), fmaxf(v2, v3)));
    }

    red[tid] = mx;
    __syncthreads();
    #pragma unroll
    for (int s = 128; s > 0; s >>= 1) {
        if (tid < s) red[tid] = fmaxf(red[tid], red[tid + s]);
        __syncthreads();
    }
    mx = red[0];
    __syncthreads();

    // exp via f16x2 EX2: 2 exps per MUFU op. (-inf - mx)*log2e = -inf -> 0.
    const float L2E = 1.4426950408889634f;
    float sum = 0.0f;
    for (int kp = tid; kp < LL / 2; kp += 256) {
        float2 v = *(float2*)&row[2 * kp];
        __half2 hx = __floats2half2_rn((v.x - mx) * L2E, (v.y - mx) * L2E);
        uint32_t hr;
        asm("ex2.approx.f16x2 %0, %1;" : "=r"(hr) : "r"(*(uint32_t*)&hx));
        float2 e = __half22float2(*(__half2*)&hr);
        *(float2*)&row[2 * kp] = e;
        sum += e.x + e.y;
    }
    red[tid] = sum;
    __syncthreads();
    #pragma unroll
    for (int s = 128; s > 0; s >>= 1) {
        if (tid < s) red[tid] += red[tid + s];
        __syncthreads();
    }
    float inv = 1.0f / red[0];
    __syncthreads();

    size_t base = ((size_t)b * LL + ii) * LL / 2;
    for (int kp = tid; kp < LL / 2; kp += 256) {
        float v0 = row[2 * kp] * inv;
        float v1 = row[2 * kp + 1] * inv;
        uint32_t hi = pack_bf16_hi(v0, v1);
        g_Pbh32[base + kp] = hi;
        g_Pbl32[base + kp] = pack_bf16_lo(v0, v1, hi);
    }
}

// ---------------------------------------------------------------------------
// Kernel 4a: shift GEMM stage 1 (tensor cores, K-split 4, partials).
// ---------------------------------------------------------------------------
#define SH_PH 0
#define SH_PL 8192
#define SH_FH 16384
#define SH_FL 24576

__global__ __launch_bounds__(256) void k_shift1() {
    __shared__ char smem[32768];
    uint32_t sbase = smem_u32(smem);

    int i0 = blockIdx.x * 64;
    int ks = blockIdx.y;
    int b  = blockIdx.z;
    if (i0 >= g_nflag) return;

    int tid  = threadIdx.x;
    int wid  = tid >> 5;
    int lane = tid & 31;
    int wm = (wid >> 1) * 16;
    int wn = (wid & 1) * 32;
    int j  = lane & 7;
    int g  = lane >> 3;

    float acc[4][4];
    #pragma unroll
    for (int t = 0; t < 4; t++)
        #pragma unroll
        for (int q = 0; q < 4; q++) acc[t][q] = 0.0f;

    for (int kc = 0; kc < 16; kc++) {
        int kb0 = ks * 1024 + kc * 64;
        __syncthreads();
        #pragma unroll
        for (int i = 0; i < 8; i++) {
            int e  = tid + i * 256;
            int r  = e >> 5;
            int cp = e & 31;
            size_t pidx = ((size_t)(b * LL + i0 + r) * LL + kb0) / 2 + cp;
            size_t fidx = ((size_t)(b * 64 + r) * LL + kb0) / 2 + cp;
            uint32_t off = SW128((uint32_t)(r * 128 + cp * 4));
            *(uint32_t*)(smem + SH_PH + off) = g_Pbh32[pidx];
            *(uint32_t*)(smem + SH_PL + off) = g_Pbl32[pidx];
            *(uint32_t*)(smem + SH_FH + off) = g_Fbh32[fidx];
            *(uint32_t*)(smem + SH_FL + off) = g_Fbl32[fidx];
        }
        __syncthreads();

        #pragma unroll
        for (int ksub = 0; ksub < 4; ksub++) {
            int kb = ksub * 32;
            uint32_t a_hi[4], a_lo[4], b_hi[2][4], b_lo[2][4];
            {
                uint32_t row = wm + (g & 1) * 8 + j;
                uint32_t off = SW128(row * 128 + kb + (g >> 1) * 16);
                ldsm_x4(a_hi, sbase + SH_PH + off);
                ldsm_x4(a_lo, sbase + SH_PL + off);
            }
            #pragma unroll
            for (int tp = 0; tp < 2; tp++) {
                uint32_t row = wn + tp * 16 + (g >> 1) * 8 + j;
                uint32_t off = SW128(row * 128 + kb + (g & 1) * 16);
                ldsm_x4(b_hi[tp], sbase + SH_FH + off);
                ldsm_x4(b_lo[tp], sbase + SH_FL + off);
            }
            #pragma unroll
            for (int t = 0; t < 4; t++) {
                const uint32_t* bh = &b_hi[t >> 1][(t & 1) * 2];
                const uint32_t* bl = &b_lo[t >> 1][(t & 1) * 2];
                mma_bf16(acc[t], a_hi, bh);
                mma_bf16(acc[t], a_hi, bl);
                mma_bf16(acc[t], a_lo, bh);
            }
        }
    }

    float* part = g_part + (size_t)(b * 4 + ks) * LL * 64;
    #pragma unroll
    for (int t = 0; t < 4; t++) {
        #pragma unroll
        for (int q = 0; q < 4; q++) {
            int row = wm + (lane >> 2) + ((q >= 2) ? 8 : 0);
            int ch  = wn + t * 8 + (lane & 3) * 2 + (q & 1);
            part[(size_t)(i0 + row) * 64 + ch] = acc[t][q];
        }
    }
}

// ---------------------------------------------------------------------------
// Kernel 4b: shift stage 2 — sum 4 K-split partials, scatter to out.
// ---------------------------------------------------------------------------
__global__ __launch_bounds__(256) void k_shift2(float* __restrict__ out) {
    int idx = blockIdx.x * 256 + threadIdx.x;
    int ch = idx & 63;
    int ii = (idx >> 6) & (LL - 1);
    int b  = idx >> 18;
    if (ii >= g_nflag) return;
    float s = 0.0f;
    #pragma unroll
    for (int ks = 0; ks < 4; ks++)
        s += g_part[(size_t)(b * 4 + ks) * LL * 64 + (size_t)ii * 64 + ch];
    int l = g_list[ii];
    out[((size_t)b * 192 + 128 + ch) * LL + l] = s;
}

// ---------------------------------------------------------------------------
extern "C" void kernel_launch(void* const* d_in, const int* in_sizes, int n_in,
                              void* d_out, int out_size) {
    const float* x    = (const float*)d_in[0];   // (2,128,64,64)
    const float* mask = (const float*)d_in[1];   // (1,1,64,64)
    float* out = (float*)d_out;                  // (2,192,64,64)

    {
        int total = BB * 192 * LL;
        k_init_out<<<(total + 255) / 256, 256>>>(x, out);
    }
    {
        int total = BB * 64 * (LL / 2);
        k_fconv<<<(total + 255) / 256, 256>>>(x);
    }
    {
        int total = BB * LL;
        k_prep<<<(total + 255) / 256, 256>>>(x, mask);
    }
    k_compact<<<1, 256>>>();
    {
        cudaFuncSetAttribute(k_gemm_mma, cudaFuncAttributeMaxDynamicSharedMemorySize, SM_DYN);
        dim3 grid(NT * (NT + 1) / 2, BB);   // 528 upper tiles x batch
        k_gemm_mma<<<grid, 256, SM_DYN>>>(x);
    }
    {
        dim3 grid(LL, BB);
        k_softmax<<<grid, 256>>>();
    }
    {
        dim3 grid(LL / 64, 4, BB);
        k_shift1<<<grid, 256>>>();
    }
    {
        int total = BB * LL * 64;
        k_shift2<<<total / 256, 256>>>(out);
    }
}